// round 16
// baseline (speedup 1.0000x reference)
#include <cuda_runtime.h>
#include <cuda_bf16.h>
#include <math.h>
#include <stdint.h>

#define BB 4
#define TT 4096
#define CC 2048
#define HH 128
#define NROW (BB * TT)          // 16384

// Scratch: K,Q stored as bf16 bits; V as tf32-rounded fp32.
__device__ uint16_t g_qb[NROW * HH];
__device__ uint16_t g_kb[NROW * HH];
__device__ float    g_v[NROW * HH];
// Stream-K partial accumulators: numerator and softmax denominator.
__device__ float    g_on[NROW * HH];
__device__ float    g_l[NROW];

// ---------------------------------------------------------------------------
// helpers
// ---------------------------------------------------------------------------
__device__ __forceinline__ float ftf32(float x) {
    uint32_t u;
    asm("cvt.rna.tf32.f32 %0, %1;" : "=r"(u) : "f"(x));
    return __uint_as_float(u);
}

__device__ __forceinline__ uint32_t bf16pair(float lo, float hi) {
    uint32_t r;
    asm("cvt.rn.bf16x2.f32 %0, %1, %2;" : "=r"(r) : "f"(hi), "f"(lo));
    return r;
}

__device__ __forceinline__ void mma_tf32(float* d, const float* a, const float* b) {
    asm volatile(
        "mma.sync.aligned.m16n8k8.row.col.f32.tf32.tf32.f32 "
        "{%0,%1,%2,%3}, {%4,%5,%6,%7}, {%8,%9}, {%0,%1,%2,%3};"
        : "+f"(d[0]), "+f"(d[1]), "+f"(d[2]), "+f"(d[3])
        : "r"(__float_as_uint(a[0])), "r"(__float_as_uint(a[1])),
          "r"(__float_as_uint(a[2])), "r"(__float_as_uint(a[3])),
          "r"(__float_as_uint(b[0])), "r"(__float_as_uint(b[1])));
}

__device__ __forceinline__ void mma_bf16(float* d, const uint32_t* a, const uint32_t* b) {
    asm volatile(
        "mma.sync.aligned.m16n8k16.row.col.f32.bf16.bf16.f32 "
        "{%0,%1,%2,%3}, {%4,%5,%6,%7}, {%8,%9}, {%0,%1,%2,%3};"
        : "+f"(d[0]), "+f"(d[1]), "+f"(d[2]), "+f"(d[3])
        : "r"(a[0]), "r"(a[1]), "r"(a[2]), "r"(a[3]),
          "r"(b[0]), "r"(b[1]));
}

__device__ __forceinline__ uint32_t smem_u32(const void* p) {
    uint32_t a;
    asm("{ .reg .u64 t; cvta.to.shared.u64 t, %1; cvt.u32.u64 %0, t; }"
        : "=r"(a) : "l"(p));
    return a;
}

__device__ __forceinline__ void cp16(uint32_t s, const void* g) {
    asm volatile("cp.async.cg.shared.global [%0], [%1], 16;" :: "r"(s), "l"(g));
}
#define CP_COMMIT() asm volatile("cp.async.commit_group;" ::: "memory")
#define CP_WAIT(n)  asm volatile("cp.async.wait_group %0;" :: "n"(n) : "memory")

// ---------------------------------------------------------------------------
// Kernel 1a: K/Q projections in bf16 (m16n8k16).  BM=128, BN=128, BK=32.
// ---------------------------------------------------------------------------
#define QBK 32
#define KQW 40      // u16 row stride

__global__ __launch_bounds__(256, 2)
void qkv_kq_kernel(const float* __restrict__ idx,
                   const float* __restrict__ Wq,
                   const float* __restrict__ Wk)
{
    __shared__ uint16_t As[128][KQW];
    __shared__ uint16_t Bs[128][KQW];

    const int w = blockIdx.y;
    const float* __restrict__ Wp = (w == 0) ? Wq : Wk;
    uint16_t* __restrict__ Out = (w == 0) ? g_qb : g_kb;

    const int row0 = blockIdx.x * 128;
    const int tid  = threadIdx.x;
    const int warp = tid >> 5, lane = tid & 31;
    const int grp  = lane >> 2, lq = lane & 3;
    const int wm   = warp >> 1;
    const int wn   = warp & 1;

    int lm[4], lk[4];
#pragma unroll
    for (int i = 0; i < 4; i++) {
        int fi = tid + 256 * i;
        lm[i] = fi >> 3;
        lk[i] = (fi & 7) * 4;
    }

    float4 ra[4], rb[4];
#pragma unroll
    for (int i = 0; i < 4; i++) {
        ra[i] = *(const float4*)(idx + (size_t)(row0 + lm[i]) * CC + lk[i]);
        rb[i] = *(const float4*)(Wp + (size_t)lm[i] * CC + lk[i]);
    }
#pragma unroll
    for (int i = 0; i < 4; i++) {
        *(uint2*)&As[lm[i]][lk[i]] =
            make_uint2(bf16pair(ra[i].x, ra[i].y), bf16pair(ra[i].z, ra[i].w));
        *(uint2*)&Bs[lm[i]][lk[i]] =
            make_uint2(bf16pair(rb[i].x, rb[i].y), bf16pair(rb[i].z, rb[i].w));
    }
    __syncthreads();

    float acc[2][8][4];
#pragma unroll
    for (int mt = 0; mt < 2; mt++)
#pragma unroll
        for (int nt = 0; nt < 8; nt++)
#pragma unroll
            for (int r = 0; r < 4; r++) acc[mt][nt][r] = 0.f;

    for (int k0 = 0; k0 < CC; k0 += QBK) {
        const int kn = k0 + QBK;
        if (kn < CC) {
#pragma unroll
            for (int i = 0; i < 4; i++) {
                ra[i] = *(const float4*)(idx + (size_t)(row0 + lm[i]) * CC + kn + lk[i]);
                rb[i] = *(const float4*)(Wp + (size_t)lm[i] * CC + kn + lk[i]);
            }
        }

#pragma unroll
        for (int kk = 0; kk < 2; kk++) {
            const int ke = kk * 16 + 2 * lq;
            uint32_t a[2][4], b[8][2];
#pragma unroll
            for (int mt = 0; mt < 2; mt++) {
                int m = wm * 32 + mt * 16 + grp;
                a[mt][0] = *(const uint32_t*)&As[m][ke];
                a[mt][1] = *(const uint32_t*)&As[m + 8][ke];
                a[mt][2] = *(const uint32_t*)&As[m][ke + 8];
                a[mt][3] = *(const uint32_t*)&As[m + 8][ke + 8];
            }
#pragma unroll
            for (int nt = 0; nt < 8; nt++) {
                int n = wn * 64 + nt * 8 + grp;
                b[nt][0] = *(const uint32_t*)&Bs[n][ke];
                b[nt][1] = *(const uint32_t*)&Bs[n][ke + 8];
            }
#pragma unroll
            for (int mt = 0; mt < 2; mt++)
#pragma unroll
                for (int nt = 0; nt < 8; nt++)
                    mma_bf16(acc[mt][nt], a[mt], b[nt]);
        }
        __syncthreads();

        if (kn < CC) {
#pragma unroll
            for (int i = 0; i < 4; i++) {
                *(uint2*)&As[lm[i]][lk[i]] =
                    make_uint2(bf16pair(ra[i].x, ra[i].y), bf16pair(ra[i].z, ra[i].w));
                *(uint2*)&Bs[lm[i]][lk[i]] =
                    make_uint2(bf16pair(rb[i].x, rb[i].y), bf16pair(rb[i].z, rb[i].w));
            }
            __syncthreads();
        }
    }

#pragma unroll
    for (int mt = 0; mt < 2; mt++)
#pragma unroll
        for (int nt = 0; nt < 8; nt++) {
            int r = row0 + wm * 32 + mt * 16 + grp;
            int c = wn * 64 + nt * 8 + 2 * lq;
            *(uint32_t*)&Out[(size_t)r * HH + c] = bf16pair(acc[mt][nt][0], acc[mt][nt][1]);
            *(uint32_t*)&Out[(size_t)(r + 8) * HH + c] = bf16pair(acc[mt][nt][2], acc[mt][nt][3]);
        }
}

// ---------------------------------------------------------------------------
// Kernel 1b: V projection in tf32.  BM=64 -> 256 CTAs.
// ---------------------------------------------------------------------------
#define VKS 36

__global__ __launch_bounds__(256, 2)
void qkv_v_kernel(const float* __restrict__ idx,
                  const float* __restrict__ Wv)
{
    __shared__ float As[64][VKS];
    __shared__ float Bs[128][VKS];

    const int row0 = blockIdx.x * 64;
    const int tid  = threadIdx.x;
    const int warp = tid >> 5, lane = tid & 31;
    const int grp  = lane >> 2, lq = lane & 3;
    const int wm   = warp >> 1;
    const int wn   = warp & 1;

    int am[2], ak[2], bm[4], bk[4];
#pragma unroll
    for (int i = 0; i < 2; i++) {
        int fi = tid + 256 * i;
        am[i] = fi >> 3;
        ak[i] = (fi & 7) * 4;
    }
#pragma unroll
    for (int i = 0; i < 4; i++) {
        int fi = tid + 256 * i;
        bm[i] = fi >> 3;
        bk[i] = (fi & 7) * 4;
    }

    float4 ra[2], rb[4];
#pragma unroll
    for (int i = 0; i < 2; i++)
        ra[i] = *(const float4*)(idx + (size_t)(row0 + am[i]) * CC + ak[i]);
#pragma unroll
    for (int i = 0; i < 4; i++)
        rb[i] = *(const float4*)(Wv + (size_t)bm[i] * CC + bk[i]);
#pragma unroll
    for (int i = 0; i < 2; i++)
        *(float4*)&As[am[i]][ak[i]] =
            make_float4(ftf32(ra[i].x), ftf32(ra[i].y), ftf32(ra[i].z), ftf32(ra[i].w));
#pragma unroll
    for (int i = 0; i < 4; i++)
        *(float4*)&Bs[bm[i]][bk[i]] =
            make_float4(ftf32(rb[i].x), ftf32(rb[i].y), ftf32(rb[i].z), ftf32(rb[i].w));
    __syncthreads();

    float acc[8][4];
#pragma unroll
    for (int nt = 0; nt < 8; nt++)
#pragma unroll
        for (int r = 0; r < 4; r++) acc[nt][r] = 0.f;

    for (int k0 = 0; k0 < CC; k0 += QBK) {
        const int kn = k0 + QBK;
        if (kn < CC) {
#pragma unroll
            for (int i = 0; i < 2; i++)
                ra[i] = *(const float4*)(idx + (size_t)(row0 + am[i]) * CC + kn + ak[i]);
#pragma unroll
            for (int i = 0; i < 4; i++)
                rb[i] = *(const float4*)(Wv + (size_t)bm[i] * CC + kn + bk[i]);
        }

#pragma unroll
        for (int kk = 0; kk < 4; kk++) {
            const int kb = kk * 8;
            float a[4], b[8][2];
            {
                int m = wm * 16 + grp;
                a[0] = As[m][kb + lq];
                a[1] = As[m + 8][kb + lq];
                a[2] = As[m][kb + lq + 4];
                a[3] = As[m + 8][kb + lq + 4];
            }
#pragma unroll
            for (int nt = 0; nt < 8; nt++) {
                int n = wn * 64 + nt * 8 + grp;
                b[nt][0] = Bs[n][kb + lq];
                b[nt][1] = Bs[n][kb + lq + 4];
            }
#pragma unroll
            for (int nt = 0; nt < 8; nt++)
                mma_tf32(acc[nt], a, b[nt]);
        }
        __syncthreads();

        if (kn < CC) {
#pragma unroll
            for (int i = 0; i < 2; i++)
                *(float4*)&As[am[i]][ak[i]] =
                    make_float4(ftf32(ra[i].x), ftf32(ra[i].y), ftf32(ra[i].z), ftf32(ra[i].w));
#pragma unroll
            for (int i = 0; i < 4; i++)
                *(float4*)&Bs[bm[i]][bk[i]] =
                    make_float4(ftf32(rb[i].x), ftf32(rb[i].y), ftf32(rb[i].z), ftf32(rb[i].w));
            __syncthreads();
        }
    }

#pragma unroll
    for (int nt = 0; nt < 8; nt++) {
        int r = row0 + wm * 16 + grp;
        int c = wn * 64 + nt * 8 + 2 * lq;
        *(float2*)&g_v[(size_t)r * HH + c] =
            make_float2(ftf32(acc[nt][0]), ftf32(acc[nt][1]));
        *(float2*)&g_v[(size_t)(r + 8) * HH + c] =
            make_float2(ftf32(acc[nt][2]), ftf32(acc[nt][3]));
    }
}

// ---------------------------------------------------------------------------
// Zero accumulators.
// ---------------------------------------------------------------------------
__global__ void zero_kernel()
{
    int i = blockIdx.x * 256 + threadIdx.x;           // float4 index
    ((float4*)g_on)[i] = make_float4(0.f, 0.f, 0.f, 0.f);
    if (i < NROW / 4)
        ((float4*)g_l)[i] = make_float4(0.f, 0.f, 0.f, 0.f);
}

// ---------------------------------------------------------------------------
// Kernel 2: stream-K causal attention, additive no-max softmax partials.
// Global work space: 4 batches x blocks ib (AM=64 rows) x j-tiles (AN=128).
// c(ib) = (ib>>1)+1 tiles, prefix S(ib) = ceil((ib+1)/2)*ceil((ib+2)/2),
// per-batch total 1056, TOT=4224, grid=148 -> 28.5 tiles/CTA.
// Partials atomicAdd'ed into g_on / g_l; div_kernel finishes.
// ---------------------------------------------------------------------------
#define AM 64
#define AN 128
#define KQST 136     // u16 row stride for Kb/Qb
#define VST2 136     // float row stride for Vs

#define SM_KB   0                         // u16  [64][136]   = 17408
#define SM_QB0  17408                     // u16  [128][136]  = 34816
#define SM_QB1  52224                     // u16  [128][136]  = 34816
#define SM_VS   87040                     // f32  [128][136]  = 69632
#define ATTN_SMEM_BYTES 156672

#define SK_TOT 4224
#define SK_NC  148
#define SFN(ib) ((((ib) + 1) >> 1) * (((ib) + 2) >> 1))

__global__ __launch_bounds__(256, 1)
void attn_kernel()
{
    extern __shared__ char smc[];
    uint16_t* Kb = (uint16_t*)(smc + SM_KB);
    float* Vs = (float*)(smc + SM_VS);
    const uint32_t sb = smem_u32(smc);

    const int tid  = threadIdx.x;
    const int warp = tid >> 5, lane = tid & 31;
    const int grp  = lane >> 2, lq = lane & 3;
    const int wm   = warp >> 2;            // 0..1 -> rows wm*32
    const int wn   = warp & 3;             // 0..3 -> j-slice wn*32
    const int srcA = (lane & ~3) + (lq >> 1);
    const int srcB = srcA + 2;
    const uint32_t FULL = 0xffffffffu;

    const float scale = rsqrtf((float)CC);

    // per-thread cp.async coords
    int qr[8], qc[8];
#pragma unroll
    for (int it = 0; it < 8; it++) {
        int fi = tid + 256 * it;           // 2048 uint4 = 128 x 16
        qr[it] = fi >> 4;
        qc[it] = (fi & 15) * 8;
    }
    int vr[16], vc[16];
#pragma unroll
    for (int it = 0; it < 16; it++) {
        int fi = tid + 256 * it;           // 4096 float4 = 128 x 32
        vr[it] = fi >> 5;
        vc[it] = (fi & 31) * 4;
    }

    int u        = ((int)blockIdx.x * SK_TOT) / SK_NC;
    const int u1 = (((int)blockIdx.x + 1) * SK_TOT) / SK_NC;

    while (u < u1) {
        // ---- decode (b, ib, jt0) from flat index u ----
        const int b = u / 1056;
        const int r = u - b * 1056;
        int ib = 2 * (int)sqrtf((float)r + 0.5f) + 1;
        if (ib > 63) ib = 63;
        while (ib < 63 && SFN(ib + 1) <= r) ib++;
        while (ib > 0 && SFN(ib) > r) ib--;
        const int jt0 = r - SFN(ib);
        const int c   = (ib >> 1) + 1;
        int take = c - jt0;
        if (take > u1 - u) take = u1 - u;
        const int jend = jt0 + take;
        u += take;

        const int i0 = ib * AM;

        __syncthreads();                    // prior segment done with smem

        // ---- load resident K tile ----
        const uint16_t* kbp = g_kb + ((size_t)b * TT + i0) * HH;
#pragma unroll
        for (int it = 0; it < 4; it++) {
            int fi = tid + 256 * it;
            int rr = fi >> 4;
            int cc = (fi & 15) * 8;
            *(uint4*)&Kb[rr * KQST + cc] = *(const uint4*)(kbp + (size_t)rr * HH + cc);
        }

        // ---- prefetch Q tile jt0 ----
        {
            const uint32_t qb0 = (jt0 & 1) ? SM_QB1 : SM_QB0;
            const uint16_t* qbp = g_qb + ((size_t)b * TT + (size_t)jt0 * AN) * HH;
#pragma unroll
            for (int it = 0; it < 8; it++)
                cp16(sb + qb0 + (qr[it] * KQST + qc[it]) * 2,
                     qbp + (size_t)qr[it] * HH + qc[it]);
            CP_COMMIT();
        }

        float o[2][16][4];
#pragma unroll
        for (int mt = 0; mt < 2; mt++)
#pragma unroll
            for (int nh = 0; nh < 16; nh++)
#pragma unroll
                for (int rg = 0; rg < 4; rg++) o[mt][nh][rg] = 0.f;
        float lsum[2][2] = {{0.f, 0.f}, {0.f, 0.f}};

        for (int jb = jt0; jb < jend; jb++) {
            const int j0 = jb * AN;
            uint16_t* Qb = (uint16_t*)(smc + ((jb & 1) ? SM_QB1 : SM_QB0));

            __syncthreads();                // prev PV done with Vs

            // ---- issue V(jb) ----
            {
                const float* vbp = g_v + ((size_t)b * TT + j0) * HH;
#pragma unroll
                for (int it = 0; it < 16; it++)
                    cp16(sb + SM_VS + (vr[it] * VST2 + vc[it]) * 4,
                         vbp + (size_t)vr[it] * HH + vc[it]);
                CP_COMMIT();
            }

            CP_WAIT(1);                     // Q(jb) done
            __syncthreads();

            // ---- S = K . Q^T ----
            float sfr[2][4][4];
#pragma unroll
            for (int mt = 0; mt < 2; mt++)
#pragma unroll
                for (int nt = 0; nt < 4; nt++)
#pragma unroll
                    for (int rg = 0; rg < 4; rg++) sfr[mt][nt][rg] = 0.f;

#pragma unroll
            for (int kk = 0; kk < 8; kk++) {
                const int ke = kk * 16 + 2 * lq;
                uint32_t a[2][4], bq[4][2];
#pragma unroll
                for (int mt = 0; mt < 2; mt++) {
                    int m = wm * 32 + mt * 16 + grp;
                    a[mt][0] = *(const uint32_t*)&Kb[m * KQST + ke];
                    a[mt][1] = *(const uint32_t*)&Kb[(m + 8) * KQST + ke];
                    a[mt][2] = *(const uint32_t*)&Kb[m * KQST + ke + 8];
                    a[mt][3] = *(const uint32_t*)&Kb[(m + 8) * KQST + ke + 8];
                }
#pragma unroll
                for (int nt = 0; nt < 4; nt++) {
                    int n = wn * 32 + nt * 8 + grp;
                    bq[nt][0] = *(const uint32_t*)&Qb[n * KQST + ke];
                    bq[nt][1] = *(const uint32_t*)&Qb[n * KQST + ke + 8];
                }
#pragma unroll
                for (int mt = 0; mt < 2; mt++)
#pragma unroll
                    for (int nt = 0; nt < 4; nt++)
                        mma_bf16(sfr[mt][nt], a[mt], bq[nt]);
            }

            // ---- issue Q(jb+1) ----
            if (jb + 1 < jend) {
                const uint32_t qn = (jb & 1) ? SM_QB0 : SM_QB1;
                const uint16_t* qbp = g_qb + ((size_t)b * TT + (size_t)(jb + 1) * AN) * HH;
#pragma unroll
                for (int it = 0; it < 8; it++)
                    cp16(sb + qn + (qr[it] * KQST + qc[it]) * 2,
                         qbp + (size_t)qr[it] * HH + qc[it]);
            }
            CP_COMMIT();

            // ---- P = exp(scale*S), causal mask, l accumulate ----
#pragma unroll
            for (int mt = 0; mt < 2; mt++) {
                const int ig0 = i0 + wm * 32 + mt * 16 + grp;
#pragma unroll
                for (int nt = 0; nt < 4; nt++) {
                    const int jg = j0 + wn * 32 + nt * 8 + 2 * lq;
                    float p0 = (jg     <= ig0    ) ? ftf32(__expf(sfr[mt][nt][0] * scale)) : 0.f;
                    float p1 = (jg + 1 <= ig0    ) ? ftf32(__expf(sfr[mt][nt][1] * scale)) : 0.f;
                    float p2 = (jg     <= ig0 + 8) ? ftf32(__expf(sfr[mt][nt][2] * scale)) : 0.f;
                    float p3 = (jg + 1 <= ig0 + 8) ? ftf32(__expf(sfr[mt][nt][3] * scale)) : 0.f;
                    sfr[mt][nt][0] = p0; sfr[mt][nt][1] = p1;
                    sfr[mt][nt][2] = p2; sfr[mt][nt][3] = p3;
                    lsum[mt][0] += p0 + p1;
                    lsum[mt][1] += p2 + p3;
                }
            }

            CP_WAIT(1);                     // V(jb) done
            __syncthreads();

            // ---- O += P @ V ----
#pragma unroll
            for (int kk = 0; kk < 4; kk++) {
                float a[2][4];
#pragma unroll
                for (int mt = 0; mt < 2; mt++) {
                    float x0 = __shfl_sync(FULL, sfr[mt][kk][0], srcA);
                    float x1 = __shfl_sync(FULL, sfr[mt][kk][1], srcA);
                    float x2 = __shfl_sync(FULL, sfr[mt][kk][2], srcA);
                    float x3 = __shfl_sync(FULL, sfr[mt][kk][3], srcA);
                    float y0 = __shfl_sync(FULL, sfr[mt][kk][0], srcB);
                    float y1 = __shfl_sync(FULL, sfr[mt][kk][1], srcB);
                    float y2 = __shfl_sync(FULL, sfr[mt][kk][2], srcB);
                    float y3 = __shfl_sync(FULL, sfr[mt][kk][3], srcB);
                    a[mt][0] = (lq & 1) ? x1 : x0;
                    a[mt][1] = (lq & 1) ? x3 : x2;
                    a[mt][2] = (lq & 1) ? y1 : y0;
                    a[mt][3] = (lq & 1) ? y3 : y2;
                }
                const int jr = wn * 32 + kk * 8;
#pragma unroll
                for (int nh = 0; nh < 16; nh++) {
                    float bv[2];
                    int h = nh * 8 + grp;
                    bv[0] = Vs[(jr + lq) * VST2 + h];
                    bv[1] = Vs[(jr + lq + 4) * VST2 + h];
#pragma unroll
                    for (int mt = 0; mt < 2; mt++)
                        mma_tf32(o[mt][nh], a[mt], bv);
                }
            }
        }

        CP_WAIT(0);                         // drain (stale empty groups)

        // ---- emit partials: l then O via atomicAdd ----
#pragma unroll
        for (int mt = 0; mt < 2; mt++)
#pragma unroll
            for (int hh = 0; hh < 2; hh++) {
                lsum[mt][hh] += __shfl_xor_sync(FULL, lsum[mt][hh], 1);
                lsum[mt][hh] += __shfl_xor_sync(FULL, lsum[mt][hh], 2);
            }
        if (lq == 0) {
#pragma unroll
            for (int mt = 0; mt < 2; mt++) {
                int rr = i0 + wm * 32 + mt * 16 + grp;
                atomicAdd(&g_l[(size_t)b * TT + rr], lsum[mt][0]);
                atomicAdd(&g_l[(size_t)b * TT + rr + 8], lsum[mt][1]);
            }
        }

#pragma unroll
        for (int mt = 0; mt < 2; mt++) {
            int rr = i0 + wm * 32 + mt * 16 + grp;
            float* p0 = g_on + ((size_t)b * TT + rr) * HH;
            float* p1 = g_on + ((size_t)b * TT + rr + 8) * HH;
#pragma unroll
            for (int nh = 0; nh < 16; nh++) {
                int h = nh * 8 + 2 * lq;
                atomicAdd(p0 + h,     o[mt][nh][0]);
                atomicAdd(p0 + h + 1, o[mt][nh][1]);
                atomicAdd(p1 + h,     o[mt][nh][2]);
                atomicAdd(p1 + h + 1, o[mt][nh][3]);
            }
        }
    }
}

// ---------------------------------------------------------------------------
// Finalize: out = g_on / g_l (broadcast per row).
// ---------------------------------------------------------------------------
__global__ void div_kernel(float* __restrict__ out)
{
    int i = blockIdx.x * 256 + threadIdx.x;           // float4 index
    int row = i >> 5;                                  // HH/4 = 32 f4 per row
    float inv = 1.f / g_l[row];
    float4 v = ((const float4*)g_on)[i];
    v.x *= inv; v.y *= inv; v.z *= inv; v.w *= inv;
    ((float4*)out)[i] = v;
}

// ---------------------------------------------------------------------------
extern "C" void kernel_launch(void* const* d_in, const int* in_sizes, int n_in,
                              void* d_out, int out_size)
{
    const float* idx = (const float*)d_in[0];
    const float* Wq  = (const float*)d_in[1];
    const float* Wk  = (const float*)d_in[2];
    const float* Wv  = (const float*)d_in[3];
    float* out = (float*)d_out;

    cudaFuncSetAttribute(attn_kernel,
                         cudaFuncAttributeMaxDynamicSharedMemorySize,
                         ATTN_SMEM_BYTES);

    zero_kernel<<<NROW * HH / 4 / 256, 256>>>();
    qkv_kq_kernel<<<dim3(NROW / 128, 2), 256>>>(idx, Wq, Wk);
    qkv_v_kernel<<<NROW / 64, 256>>>(idx, Wv);
    attn_kernel<<<SK_NC, 256, ATTN_SMEM_BYTES>>>();
    div_kernel<<<NROW * HH / 4 / 256, 256>>>(out);
}